// round 4
// baseline (speedup 1.0000x reference)
#include <cuda_runtime.h>
#include <cuda_bf16.h>
#include <math.h>

// Problem dims (fixed by setup_inputs)
#define BB 64
#define KK 8
#define FF 24
#define DD 32   // KK + FF
#define HH 64
#define LL 2048
#define CC 64
#define XAUG_ELEMS (BB * LL * CC)   // 8388608

#define TPB   256                       // threads per block
#define ITERS 8                         // float4 per thread
#define V4_PER_BATCH (LL * CC / 4)      // 32768
#define V4_PER_BLOCK (TPB * ITERS)      // 2048
#define BPB (V4_PER_BATCH / V4_PER_BLOCK) // 16 blocks per batch

// ---------------------------------------------------------------------------
// Single fused kernel.
//  - All threads prefetch their 8 float4 of x (addresses are k-independent:
//    the k==7 time-flip is applied on the STORE side, values unchanged).
//  - Threads 0-63 run the prob MLP, threads 64-127 run the intensity MLP
//    concurrently (independent networks) while the x loads are in flight.
//  - Thread 0 does softmax / softplus-gather / gumbel-argmax; selection is
//    exactly one-hot (y_soft - stop_grad(y_soft) == 0), so only the selected
//    transform is applied.
//  - blockIdx.x==0 blocks also write the small tail outputs.
// ---------------------------------------------------------------------------
__global__ void __launch_bounds__(TPB) fused_kernel(
    const float* __restrict__ x,
    const float* __restrict__ prev_prob,   // (B,K)
    const float* __restrict__ features,    // (B,F)
    const float* __restrict__ gumbel,      // (B,K)
    const float* __restrict__ pW1, const float* __restrict__ pb1,
    const float* __restrict__ pW2, const float* __restrict__ pb2,
    const float* __restrict__ pW3, const float* __restrict__ pb3,
    const float* __restrict__ iW1, const float* __restrict__ ib1,
    const float* __restrict__ iW2, const float* __restrict__ ib2,
    const float* __restrict__ iW3, const float* __restrict__ ib3,
    float* __restrict__ out,
    float* __restrict__ out_prob,          // (B,K)
    float* __restrict__ out_int,           // (B,K)
    float* __restrict__ out_sel)           // (B,)
{
    const int b   = blockIdx.y;
    const int tid = threadIdx.x;

    __shared__ float s_in[DD];
    __shared__ float hp1[HH], hp2[HH];     // prob MLP hiddens
    __shared__ float hi1[HH], hi2[HH];     // intensity MLP hiddens
    __shared__ float s_logit[KK];
    __shared__ float s_int[KK];
    __shared__ int   s_ki;
    __shared__ float s_t;

    // ---- prefetch x: 8 independent float4 loads, issued before any sync ----
    const float4* __restrict__ xi = (const float4*)(x + (size_t)b * LL * CC);
    const int base = blockIdx.x * V4_PER_BLOCK + tid;
    float4 v[ITERS];
    #pragma unroll
    for (int j = 0; j < ITERS; j++) v[j] = xi[base + j * TPB];

    // ---- stage MLP input ----
    if (tid < KK)       s_in[tid] = prev_prob[b * KK + tid];
    else if (tid < DD)  s_in[tid] = features[b * FF + (tid - KK)];
    __syncthreads();

    // ---- two MLPs in parallel: threads 0-63 prob, 64-127 intensity ----
    const int  lt  = tid & 63;
    const bool isP = (tid < 64);
    const bool act = (tid < 128);

    if (act) {
        const float* W1 = isP ? pW1 : iW1;  const float* b1 = isP ? pb1 : ib1;
        float* h1 = isP ? hp1 : hi1;
        float a = b1[lt];
        #pragma unroll
        for (int i = 0; i < DD; i++) a = fmaf(s_in[i], W1[i * HH + lt], a);
        h1[lt] = fmaxf(a, 0.f);
    }
    __syncthreads();
    if (act) {
        const float* W2 = isP ? pW2 : iW2;  const float* b2 = isP ? pb2 : ib2;
        const float* h1 = isP ? hp1 : hi1;  float* h2 = isP ? hp2 : hi2;
        float a = b2[lt];
        #pragma unroll 16
        for (int i = 0; i < HH; i++) a = fmaf(h1[i], W2[i * HH + lt], a);
        h2[lt] = fmaxf(a, 0.f);
    }
    __syncthreads();
    if (act && lt < KK) {
        const float* W3 = isP ? pW3 : iW3;  const float* b3 = isP ? pb3 : ib3;
        const float* h2 = isP ? hp2 : hi2;
        float a = b3[lt];
        #pragma unroll 16
        for (int i = 0; i < HH; i++) a = fmaf(h2[i], W3[i * KK + lt], a);
        if (isP) s_logit[lt] = a;
        else     s_int[lt]   = (a > 20.f) ? a : log1pf(expf(a));  // softplus
    }
    __syncthreads();

    if (tid == 0) {
        // argmax(logits + gumbel) == argmax(y_soft); selection is exactly one-hot
        int best = 0;
        float bv = s_logit[0] + gumbel[b * KK + 0];
        #pragma unroll
        for (int k = 1; k < KK; k++) {
            float t2 = s_logit[k] + gumbel[b * KK + k];
            if (t2 > bv) { bv = t2; best = k; }
        }
        s_ki = best;
        s_t  = s_int[best];

        if (blockIdx.x == 0) {
            // softmax over K=8 logits
            float m = s_logit[0];
            #pragma unroll
            for (int k = 1; k < KK; k++) m = fmaxf(m, s_logit[k]);
            float e[KK]; float sum = 0.f;
            #pragma unroll
            for (int k = 0; k < KK; k++) { e[k] = expf(s_logit[k] - m); sum += e[k]; }
            float inv = 1.f / sum;
            #pragma unroll
            for (int k = 0; k < KK; k++) out_prob[b * KK + k] = e[k] * inv;
            #pragma unroll
            for (int k = 0; k < KK; k++) out_int[b * KK + k] = s_int[k];
            out_sel[b] = (float)best;
        }
    }
    __syncthreads();

    const int   k = s_ki;
    const float t = s_t;
    float4* __restrict__ oo = (float4*)(out + (size_t)b * LL * CC);

    if (k == 7) {
        // time reversal: identity values, flipped store position (coalesced)
        #pragma unroll
        for (int j = 0; j < ITERS; j++) {
            int idx = base + j * TPB;
            int l   = idx >> 4;
            int c4  = idx & 15;
            __stcs(&oo[((LL - 1 - l) << 4) + c4], v[j]);
        }
    } else if (k == 4) {
        const float A = 1.f + t;
        #pragma unroll
        for (int j = 0; j < ITERS; j++) {
            float4 w = v[j];
            w.x = tanhf(w.x * A); w.y = tanhf(w.y * A);
            w.z = tanhf(w.z * A); w.w = tanhf(w.w * A);
            __stcs(&oo[base + j * TPB], w);
        }
    } else if (k == 6) {
        #pragma unroll
        for (int j = 0; j < ITERS; j++) {
            float4 w = v[j];
            w.x = fmaf(t, sinf(w.x), w.x); w.y = fmaf(t, sinf(w.y), w.y);
            w.z = fmaf(t, sinf(w.z), w.z); w.w = fmaf(t, sinf(w.w), w.w);
            __stcs(&oo[base + j * TPB], w);
        }
    } else {
        // k in {0,1,2,3,5}: affine A*x + Bc
        float A = 1.f, Bc = 0.f;
        if      (k == 1) A = 1.f + t;
        else if (k == 2) Bc = t;
        else if (k == 3) A = 1.f - t;
        else if (k == 5) A = expf(-t);
        #pragma unroll
        for (int j = 0; j < ITERS; j++) {
            float4 w = v[j];
            w.x = fmaf(w.x, A, Bc); w.y = fmaf(w.y, A, Bc);
            w.z = fmaf(w.z, A, Bc); w.w = fmaf(w.w, A, Bc);
            __stcs(&oo[base + j * TPB], w);
        }
    }
}

extern "C" void kernel_launch(void* const* d_in, const int* in_sizes, int n_in,
                              void* d_out, int out_size)
{
    const float* x         = (const float*)d_in[0];
    const float* prev_prob = (const float*)d_in[1];
    const float* features  = (const float*)d_in[2];
    const float* gumbel    = (const float*)d_in[3];
    // d_in[4] = log_temperature: dead for forward values (exact one-hot selection;
    // tau>0 never changes the argmax; prob uses the raw softmax of logits).
    const float* pW1 = (const float*)d_in[5];
    const float* pb1 = (const float*)d_in[6];
    const float* pW2 = (const float*)d_in[7];
    const float* pb2 = (const float*)d_in[8];
    const float* pW3 = (const float*)d_in[9];
    const float* pb3 = (const float*)d_in[10];
    const float* iW1 = (const float*)d_in[11];
    const float* ib1 = (const float*)d_in[12];
    const float* iW2 = (const float*)d_in[13];
    const float* ib2 = (const float*)d_in[14];
    const float* iW3 = (const float*)d_in[15];
    const float* ib3 = (const float*)d_in[16];

    float* out      = (float*)d_out;
    float* out_prob = out + XAUG_ELEMS;              // (B,K)
    float* out_int  = out_prob + BB * KK;            // (B,K)
    float* out_sel  = out_int  + BB * KK;            // (B,)

    dim3 grid(BPB, BB);   // (16, 64) = 1024 blocks
    fused_kernel<<<grid, TPB>>>(x, prev_prob, features, gumbel,
                                pW1, pb1, pW2, pb2, pW3, pb3,
                                iW1, ib1, iW2, ib2, iW3, ib3,
                                out, out_prob, out_int, out_sel);
}